// round 1
// baseline (speedup 1.0000x reference)
#include <cuda_runtime.h>

#define SEQ 8192
#define DIM 512
#define DK  64
#define BM  64
#define BN  128

// Scratch for projected Q/K/V (allocation-free: device globals).
__device__ float g_Q[SEQ * DK];
__device__ float g_K[SEQ * DK];
__device__ float g_V[SEQ * DK];

// ---------------------------------------------------------------------------
// Kernel 1: fused QKV projection.  C = x @ W  for W in {Wq, Wk, Wv} (blockIdx.y)
// Block tile: 64 rows x 64 cols, K-tiles of 64. 256 threads, 4x4 microtile.
// ---------------------------------------------------------------------------
__global__ __launch_bounds__(256, 1) void qkv_kernel(
    const float* __restrict__ x,
    const float* __restrict__ Wq,
    const float* __restrict__ Wk,
    const float* __restrict__ Wv)
{
    __shared__ float xs[64][68];   // xs[k][m]  (transposed x tile)
    __shared__ float ws[64][68];   // ws[k][n]

    const float* W;
    float* C;
    if (blockIdx.y == 0)      { W = Wq; C = g_Q; }
    else if (blockIdx.y == 1) { W = Wk; C = g_K; }
    else                      { W = Wv; C = g_V; }

    const int tid = threadIdx.x;
    const int tx = tid & 15;        // col group (4 cols)
    const int ty = tid >> 4;        // row group (4 rows)
    const int m0 = blockIdx.x * 64;

    float acc[4][4] = {};

    for (int kt = 0; kt < DIM; kt += 64) {
        // Load x tile (64 rows x 64 k), store transposed into xs[k][m].
        #pragma unroll
        for (int i = 0; i < 4; i++) {
            int f = i * 256 + tid;             // 1024 float4
            int row = f >> 4;
            int k4  = f & 15;
            float4 v = *(const float4*)(x + (size_t)(m0 + row) * DIM + kt + k4 * 4);
            xs[k4 * 4 + 0][row] = v.x;
            xs[k4 * 4 + 1][row] = v.y;
            xs[k4 * 4 + 2][row] = v.z;
            xs[k4 * 4 + 3][row] = v.w;
        }
        // Load W tile (64 k x 64 n) natural layout.
        #pragma unroll
        for (int i = 0; i < 4; i++) {
            int f = i * 256 + tid;
            int k  = f >> 4;
            int n4 = f & 15;
            *(float4*)&ws[k][n4 * 4] =
                *(const float4*)(W + (size_t)(kt + k) * DK + n4 * 4);
        }
        __syncthreads();

        #pragma unroll 16
        for (int k = 0; k < 64; k++) {
            float4 a = *(float4*)&xs[k][ty * 4];
            float4 b = *(float4*)&ws[k][tx * 4];
            float av[4] = {a.x, a.y, a.z, a.w};
            float bv[4] = {b.x, b.y, b.z, b.w};
            #pragma unroll
            for (int r = 0; r < 4; r++)
                #pragma unroll
                for (int c = 0; c < 4; c++)
                    acc[r][c] = fmaf(av[r], bv[c], acc[r][c]);
        }
        __syncthreads();
    }

    #pragma unroll
    for (int r = 0; r < 4; r++) {
        float4 v = make_float4(acc[r][0], acc[r][1], acc[r][2], acc[r][3]);
        *(float4*)(C + (size_t)(m0 + ty * 4 + r) * DK + tx * 4) = v;
    }
}

// ---------------------------------------------------------------------------
// Kernel 2: flash attention, fp32.
// Block: 64 queries. Stream KV in tiles of 128. Online softmax (m,l in regs,
// replicated across the 16-lane row group via width-16 shuffles).
// Thread map (both GEMMs): rows ty*4..+3. S cols: {tx*4..+3, 64+tx*4..+3}.
// O cols: tx*4..+3.
// ---------------------------------------------------------------------------
__global__ __launch_bounds__(256, 1) void flash_kernel(float* __restrict__ out)
{
    extern __shared__ float smem[];
    float (*Qs)[68]  = (float(*)[68])(smem);                              // 64 x 68
    float (*Ks)[132] = (float(*)[132])(smem + 64 * 68);                   // 64 x 132
    float (*Vs)[68]  = (float(*)[68])(smem + 64 * 68 + 64 * 132);         // 128 x 68
    float (*Ps)[68]  = (float(*)[68])(smem + 64 * 68 + 64 * 132 + 128 * 68); // 128 x 68

    const int tid = threadIdx.x;
    const int tx = tid & 15;
    const int ty = tid >> 4;
    const int m0 = blockIdx.x * BM;

    // Load Q tile, transposed to Qs[d][m], folding in the 1/sqrt(64) scale.
    #pragma unroll
    for (int i = 0; i < 4; i++) {
        int f = i * 256 + tid;
        int row = f >> 4;
        int d4  = f & 15;
        float4 v = *(const float4*)(g_Q + (size_t)(m0 + row) * DK + d4 * 4);
        Qs[d4 * 4 + 0][row] = v.x * 0.125f;
        Qs[d4 * 4 + 1][row] = v.y * 0.125f;
        Qs[d4 * 4 + 2][row] = v.z * 0.125f;
        Qs[d4 * 4 + 3][row] = v.w * 0.125f;
    }

    float O[4][4] = {};
    float mrow[4], lrow[4];
    #pragma unroll
    for (int r = 0; r < 4; r++) { mrow[r] = -1e30f; lrow[r] = 0.0f; }

    for (int t = 0; t < SEQ / BN; t++) {
        const int n0 = t * BN;

        // K tile -> Ks[d][n] (transposed).
        #pragma unroll
        for (int i = 0; i < 8; i++) {
            int f = i * 256 + tid;       // 2048 float4
            int row = f >> 4;            // 0..127
            int d4  = f & 15;
            float4 v = *(const float4*)(g_K + (size_t)(n0 + row) * DK + d4 * 4);
            Ks[d4 * 4 + 0][row] = v.x;
            Ks[d4 * 4 + 1][row] = v.y;
            Ks[d4 * 4 + 2][row] = v.z;
            Ks[d4 * 4 + 3][row] = v.w;
        }
        // V tile -> Vs[j][c] (natural).
        #pragma unroll
        for (int i = 0; i < 8; i++) {
            int f = i * 256 + tid;
            int j  = f >> 4;
            int c4 = f & 15;
            *(float4*)&Vs[j][c4 * 4] =
                *(const float4*)(g_V + (size_t)(n0 + j) * DK + c4 * 4);
        }
        __syncthreads();

        // S = (Q/8) @ K^T  (64x128 block tile; 4x8 per thread)
        float s[4][8] = {};
        #pragma unroll 8
        for (int d = 0; d < 64; d++) {
            float4 a  = *(float4*)&Qs[d][ty * 4];
            float4 b0 = *(float4*)&Ks[d][tx * 4];
            float4 b1 = *(float4*)&Ks[d][64 + tx * 4];
            float av[4] = {a.x, a.y, a.z, a.w};
            float bv[8] = {b0.x, b0.y, b0.z, b0.w, b1.x, b1.y, b1.z, b1.w};
            #pragma unroll
            for (int r = 0; r < 4; r++)
                #pragma unroll
                for (int c = 0; c < 8; c++)
                    s[r][c] = fmaf(av[r], bv[c], s[r][c]);
        }

        // Online softmax update per row.
        #pragma unroll
        for (int r = 0; r < 4; r++) {
            float mt = s[r][0];
            #pragma unroll
            for (int c = 1; c < 8; c++) mt = fmaxf(mt, s[r][c]);
            #pragma unroll
            for (int off = 8; off; off >>= 1)
                mt = fmaxf(mt, __shfl_xor_sync(0xffffffffu, mt, off, 16));

            float mn    = fmaxf(mrow[r], mt);
            float alpha = __expf(mrow[r] - mn);
            mrow[r] = mn;

            float rs = 0.0f;
            #pragma unroll
            for (int c = 0; c < 8; c++) {
                s[r][c] = __expf(s[r][c] - mn);
                rs += s[r][c];
            }
            #pragma unroll
            for (int off = 8; off; off >>= 1)
                rs += __shfl_xor_sync(0xffffffffu, rs, off, 16);

            lrow[r] = lrow[r] * alpha + rs;
            #pragma unroll
            for (int c = 0; c < 4; c++) O[r][c] *= alpha;
        }

        // Store P transposed: Ps[j][m] so PV reads are float4 along m.
        #pragma unroll
        for (int c = 0; c < 8; c++) {
            int col = (c < 4) ? (tx * 4 + c) : (64 + tx * 4 + (c - 4));
            float4 v = make_float4(s[0][c], s[1][c], s[2][c], s[3][c]);
            *(float4*)&Ps[col][ty * 4] = v;
        }
        __syncthreads();

        // O += P @ V  (64x64 block tile; 4x4 per thread, k = 128)
        #pragma unroll 8
        for (int j = 0; j < BN; j++) {
            float4 a = *(float4*)&Ps[j][ty * 4];
            float4 b = *(float4*)&Vs[j][tx * 4];
            float av[4] = {a.x, a.y, a.z, a.w};
            float bv[4] = {b.x, b.y, b.z, b.w};
            #pragma unroll
            for (int r = 0; r < 4; r++)
                #pragma unroll
                for (int c = 0; c < 4; c++)
                    O[r][c] = fmaf(av[r], bv[c], O[r][c]);
        }
        __syncthreads();
    }

    #pragma unroll
    for (int r = 0; r < 4; r++) {
        float inv = 1.0f / lrow[r];
        float4 v = make_float4(O[r][0] * inv, O[r][1] * inv,
                               O[r][2] * inv, O[r][3] * inv);
        *(float4*)(out + (size_t)(m0 + ty * 4 + r) * DK + tx * 4) = v;
    }
}

// ---------------------------------------------------------------------------
// Launch
// ---------------------------------------------------------------------------
extern "C" void kernel_launch(void* const* d_in, const int* in_sizes, int n_in,
                              void* d_out, int out_size)
{
    const float* x  = (const float*)d_in[0];
    const float* Wq = (const float*)d_in[1];
    const float* Wk = (const float*)d_in[2];
    const float* Wv = (const float*)d_in[3];
    float* out = (float*)d_out;

    dim3 g1(SEQ / 64, 3);
    qkv_kernel<<<g1, 256>>>(x, Wq, Wk, Wv);

    const int smem_bytes = (64 * 68 + 64 * 132 + 128 * 68 + 128 * 68) * 4; // 120832
    cudaFuncSetAttribute(flash_kernel,
                         cudaFuncAttributeMaxDynamicSharedMemorySize, smem_bytes);
    flash_kernel<<<SEQ / BM, 256, smem_bytes>>>(out);
}